// round 15
// baseline (speedup 1.0000x reference)
#include <cuda_runtime.h>
#include <cstdint>

#define TOK   200704       // 64*56*56 tokens
#define CIN   256
#define QKVD  768
#define NHEAD 8
#define HD    32
#define WT    49
#define NWIN  4096
#define SCALE 5.656854249f // sqrt(32) -- reference MULTIPLIES by sqrt(hd)

// ---------------- scratch (static device globals; no allocs allowed) -------
__device__ float g_qkv[(size_t)TOK * QKVD];
__device__ float g_att[(size_t)TOK * CIN];

// ---------------- helpers ---------------------------------------------------
// pack two floats as bf16x2: low half = lo_elem (lower k index), high = hi_elem
__device__ __forceinline__ uint32_t pack_bf16(float lo_elem, float hi_elem) {
    uint32_t d;
    asm("cvt.rn.bf16x2.f32 %0, %1, %2;" : "=r"(d) : "f"(hi_elem), "f"(lo_elem));
    return d;
}

// split (e,o) pair into bf16 hi-pair + bf16 lo-pair (residual)
__device__ __forceinline__ void split_pair(float e, float o,
                                           uint32_t& hp, uint32_t& lp) {
    hp = pack_bf16(e, o);
    float ef = __uint_as_float(hp << 16);
    float of = __uint_as_float(hp & 0xFFFF0000u);
    lp = pack_bf16(e - ef, o - of);
}

__device__ __forceinline__ void mma_bf16(float* c, const uint32_t* a,
                                         uint32_t b) {
    asm volatile(
        "mma.sync.aligned.m16n8k8.row.col.f32.bf16.bf16.f32 "
        "{%0,%1,%2,%3}, {%4,%5}, {%6}, {%0,%1,%2,%3};"
        : "+f"(c[0]), "+f"(c[1]), "+f"(c[2]), "+f"(c[3])
        : "r"(a[0]), "r"(a[1]), "r"(b));
}

// ---------------------------------------------------------------------------
// 3xBF16 mma.sync GEMM:  C[M,N] = A[M,K] @ B[K,N] + bias[N]
// BM=128, BN=128, BK=32. 256 threads = 8 warps (4 m x 2 n), warp tile 32x64.
// A,B split hi/lo bf16; C = Ah*Bh + Ah*Bl + Al*Bh, fp32 accumulate.
// Smem (u32 words, stride 20 = 16 data + 4 pad; r*20 mod 32 all-distinct):
//   A hi/lo: [128 rows][16 k-pairs]    B hi/lo: [128 n][16 k-pairs]
// ---------------------------------------------------------------------------
#define SSTR 20
#define U_AHI 0
#define U_ALO (128 * SSTR)
#define U_BHI (2 * 128 * SSTR)
#define U_BLO (3 * 128 * SSTR)
#define SMEM_WORDS (4 * 128 * SSTR)
#define SMEM_BYTES (SMEM_WORDS * 4)

__global__ __launch_bounds__(256, 2) void gemm_mma(
    int M, int N, int K,
    const float* __restrict__ A,
    const float* __restrict__ B,
    const float* __restrict__ bias,
    float* __restrict__ C)
{
    extern __shared__ uint32_t su[];
    uint32_t* sAhi = su + U_AHI;
    uint32_t* sAlo = su + U_ALO;
    uint32_t* sBhi = su + U_BHI;
    uint32_t* sBlo = su + U_BLO;

    const int tid  = threadIdx.x;
    const int lane = tid & 31;
    const int warp = tid >> 5;
    const int wm   = warp & 3;   // m offset wm*32
    const int wn   = warp >> 2;  // n offset wn*64
    const int bm   = blockIdx.x * 128;
    const int bn   = blockIdx.y * 128;

    float acc[2][8][4];
#pragma unroll
    for (int mt = 0; mt < 2; mt++)
#pragma unroll
        for (int nt = 0; nt < 8; nt++)
#pragma unroll
            for (int i = 0; i < 4; i++) acc[mt][nt][i] = 0.f;

    const int r = lane >> 2;   // 0..7
    const int q = lane & 3;    // 0..3

    for (int c = 0; c < K / 32; c++) {
        const int k0 = c * 32;
        // ---- stage A (128 rows x 32 k), split -> bf16 pairs ----
#pragma unroll
        for (int i = 0; i < 4; i++) {
            const int idx = tid + i * 256;          // 0..1023
            const int row = idx >> 3;               // 0..127
            const int qq  = idx & 7;                // float4 index (k = 4qq)
            float4 v = *(const float4*)(A + (size_t)(bm + row) * K + k0 + qq * 4);
            uint32_t h0, l0, h1, l1;
            split_pair(v.x, v.y, h0, l0);
            split_pair(v.z, v.w, h1, l1);
            uint32_t* ph = sAhi + row * SSTR + qq * 2;
            uint32_t* pl = sAlo + row * SSTR + qq * 2;
            *(uint2*)ph = make_uint2(h0, h1);
            *(uint2*)pl = make_uint2(l0, l1);
        }
        // ---- stage B (32 k x 128 n) -> n-major bf16 k-pairs ----
        // item: kp = k-pair 0..15, ng*4..+3 = n columns
#pragma unroll
        for (int i = 0; i < 2; i++) {
            const int idx2 = tid + i * 256;         // 0..511
            const int kp = idx2 & 15;               // 0..15
            const int ng = idx2 >> 4;               // 0..31
            const float* b0p = B + (size_t)(k0 + 2 * kp) * N + bn + ng * 4;
            float4 r0 = *(const float4*)b0p;
            float4 r1 = *(const float4*)(b0p + N);
#pragma unroll
            for (int j = 0; j < 4; j++) {
                float e = (&r0.x)[j];      // k = 2kp
                float o = (&r1.x)[j];      // k = 2kp+1
                uint32_t hp, lp;
                split_pair(e, o, hp, lp);
                sBhi[(ng * 4 + j) * SSTR + kp] = hp;
                sBlo[(ng * 4 + j) * SSTR + kp] = lp;
            }
        }
        __syncthreads();

        // ---- compute: 4 k8-steps ----
#pragma unroll
        for (int ks = 0; ks < 4; ks++) {
            const int kp0 = ks * 4 + q;
            uint32_t ah[2][2], al[2][2];
            {
                const int arow = wm * 32 + r;
#pragma unroll
                for (int mt = 0; mt < 2; mt++) {
                    const int base = (arow + mt * 16) * SSTR + kp0;
                    ah[mt][0] = sAhi[base];
                    ah[mt][1] = sAhi[base + 8 * SSTR];
                    al[mt][0] = sAlo[base];
                    al[mt][1] = sAlo[base + 8 * SSTR];
                }
            }
#pragma unroll
            for (int ng = 0; ng < 2; ng++) {
                uint32_t bh[4], bl[4];
                {
                    const int nbase = (wn * 64 + ng * 32 + r) * SSTR + kp0;
#pragma unroll
                    for (int nt = 0; nt < 4; nt++) {
                        bh[nt] = sBhi[nbase + nt * 8 * SSTR];
                        bl[nt] = sBlo[nbase + nt * 8 * SSTR];
                    }
                }
#pragma unroll
                for (int mt = 0; mt < 2; mt++)
#pragma unroll
                    for (int nt = 0; nt < 4; nt++) {
                        float* a4 = acc[mt][ng * 4 + nt];
                        mma_bf16(a4, ah[mt], bh[nt]);
                        mma_bf16(a4, ah[mt], bl[nt]);
                        mma_bf16(a4, al[mt], bh[nt]);
                    }
            }
        }
        __syncthreads();
    }

    // ---- epilogue: direct global stores with bias ----
#pragma unroll
    for (int mt = 0; mt < 2; mt++) {
        const int row0 = bm + wm * 32 + mt * 16 + r;
#pragma unroll
        for (int nt = 0; nt < 8; nt++) {
            const int col0 = bn + wn * 64 + nt * 8 + q * 2;
            const float2 bv = *(const float2*)(bias + col0);
            float2 o0, o1;
            o0.x = acc[mt][nt][0] + bv.x; o0.y = acc[mt][nt][1] + bv.y;
            o1.x = acc[mt][nt][2] + bv.x; o1.y = acc[mt][nt][3] + bv.y;
            *(float2*)(C + (size_t)row0 * N + col0) = o0;
            *(float2*)(C + (size_t)(row0 + 8) * N + col0) = o1;
        }
    }
}

// ---------------------------------------------------------------------------
// Windowed attention: one block per (window, head). 64 threads; threads 0..48
// each own one query row.
// ---------------------------------------------------------------------------
__global__ __launch_bounds__(64) void attn_kernel(
    const float* __restrict__ qkv,
    const float* __restrict__ pos,
    float* __restrict__ att)
{
    __shared__ float sq[WT * HD];
    __shared__ float sk[WT * HD];
    __shared__ float sv[WT * HD];
    __shared__ float ss[WT * WT];
    __shared__ float spos[169];

    const int id   = blockIdx.x;
    const int head = id & 7;
    const int j    = (id >> 3) & 7;
    const int i    = (id >> 6) & 7;
    const int b    = id >> 9;
    const int tid  = threadIdx.x;
    const int base = b * 3136 + i * 7 * 56 + j * 7;

    for (int idx = tid; idx < WT * HD; idx += 64) {
        const int t = idx >> 5, d = idx & 31;
        const size_t row = (size_t)(base + (t / 7) * 56 + (t % 7)) * QKVD
                         + head * HD + d;
        sq[idx] = qkv[row];
        sk[idx] = qkv[row + 256];
        sv[idx] = qkv[row + 512];
    }
    for (int idx = tid; idx < 169; idx += 64) spos[idx] = pos[idx];
    __syncthreads();

    if (tid < WT) {
        float qr[HD];
#pragma unroll
        for (int d = 0; d < HD; d++) qr[d] = sq[tid * HD + d];

        const int idxr = tid / 7 + tid % 7;
        const float* prow = spos + idxr * 13;
        const float4* sk4 = (const float4*)sk;
        const float4* sv4 = (const float4*)sv;

        float mx = -1e30f;
#pragma unroll 7
        for (int l = 0; l < WT; l++) {
            float a = 0.f;
#pragma unroll
            for (int d4 = 0; d4 < 8; d4++) {
                float4 kv = sk4[l * 8 + d4];
                a += qr[d4 * 4 + 0] * kv.x + qr[d4 * 4 + 1] * kv.y
                   + qr[d4 * 4 + 2] * kv.z + qr[d4 * 4 + 3] * kv.w;
            }
            a = a * SCALE + prow[l / 7 + l % 7];
            ss[tid * WT + l] = a;
            mx = fmaxf(mx, a);
        }

        float sum = 0.f;
#pragma unroll 7
        for (int l = 0; l < WT; l++) {
            float e = __expf(ss[tid * WT + l] - mx);
            ss[tid * WT + l] = e;
            sum += e;
        }
        const float inv = 1.f / sum;

        float acc[HD];
#pragma unroll
        for (int d = 0; d < HD; d++) acc[d] = 0.f;

#pragma unroll 7
        for (int l = 0; l < WT; l++) {
            const float p = ss[tid * WT + l];
#pragma unroll
            for (int d4 = 0; d4 < 8; d4++) {
                float4 vv = sv4[l * 8 + d4];
                acc[d4 * 4 + 0] += p * vv.x; acc[d4 * 4 + 1] += p * vv.y;
                acc[d4 * 4 + 2] += p * vv.z; acc[d4 * 4 + 3] += p * vv.w;
            }
        }

        const size_t orow = (size_t)(base + (tid / 7) * 56 + (tid % 7)) * CIN
                          + head * HD;
#pragma unroll
        for (int d4 = 0; d4 < 8; d4++) {
            float4 o;
            o.x = acc[d4 * 4 + 0] * inv; o.y = acc[d4 * 4 + 1] * inv;
            o.z = acc[d4 * 4 + 2] * inv; o.w = acc[d4 * 4 + 3] * inv;
            *(float4*)(att + orow + d4 * 4) = o;
        }
    }
}

// ---------------------------------------------------------------------------
extern "C" void kernel_launch(void* const* d_in, const int* in_sizes, int n_in,
                              void* d_out, int out_size)
{
    const float* x      = (const float*)d_in[0];
    const float* pos    = (const float*)d_in[1];
    const float* w_qkv  = (const float*)d_in[2];
    const float* b_qkv  = (const float*)d_in[3];
    const float* w_out  = (const float*)d_in[4];
    const float* b_out  = (const float*)d_in[5];
    float* out = (float*)d_out;

    float *qkvp, *attp;
    cudaGetSymbolAddress((void**)&qkvp, g_qkv);
    cudaGetSymbolAddress((void**)&attp, g_att);

    cudaFuncSetAttribute(gemm_mma, cudaFuncAttributeMaxDynamicSharedMemorySize,
                         SMEM_BYTES);

    // 1) qkv = x @ w_qkv + b_qkv     [200704,256]@[256,768]
    {
        dim3 grid(TOK / 128, QKVD / 128);
        gemm_mma<<<grid, 256, SMEM_BYTES>>>(TOK, QKVD, CIN, x, w_qkv, b_qkv, qkvp);
    }
    // 2) windowed attention
    attn_kernel<<<NWIN * NHEAD, 64>>>(qkvp, pos, attp);
    // 3) out = att @ w_out + b_out   [200704,256]@[256,256]
    {
        dim3 grid(TOK / 128, CIN / 128);
        gemm_mma<<<grid, 256, SMEM_BYTES>>>(TOK, CIN, CIN, attp, w_out, b_out, out);
    }
}

// round 16
// speedup vs baseline: 1.2026x; 1.2026x over previous
#include <cuda_runtime.h>
#include <cstdint>

#define TOK   200704       // 64*56*56 tokens
#define CIN   256
#define QKVD  768
#define NHEAD 8
#define HD    32
#define WT    49
#define NWIN  4096
#define SCALE 5.656854249f // sqrt(32) -- reference MULTIPLIES by sqrt(hd)

// ---------------- scratch (static device globals; no allocs allowed) -------
__device__ float g_qkv[(size_t)TOK * QKVD];
__device__ float g_att[(size_t)TOK * CIN];

// ---------------- helpers ---------------------------------------------------
// pack two floats as bf16x2: low half = lo_elem (lower k index), high = hi_elem
__device__ __forceinline__ uint32_t pack_bf16(float lo_elem, float hi_elem) {
    uint32_t d;
    asm("cvt.rn.bf16x2.f32 %0, %1, %2;" : "=r"(d) : "f"(hi_elem), "f"(lo_elem));
    return d;
}

// split (e,o) pair into bf16 hi-pair + bf16 lo-pair (residual)
__device__ __forceinline__ void split_pair(float e, float o,
                                           uint32_t& hp, uint32_t& lp) {
    hp = pack_bf16(e, o);
    float ef = __uint_as_float(hp << 16);
    float of = __uint_as_float(hp & 0xFFFF0000u);
    lp = pack_bf16(e - ef, o - of);
}

// m16n8k16 bf16 MMA: a = 4 regs, b = 2 regs, c += a*b
__device__ __forceinline__ void mma_bf16_k16(float* c, const uint32_t* a,
                                             const uint32_t* b) {
    asm volatile(
        "mma.sync.aligned.m16n8k16.row.col.f32.bf16.bf16.f32 "
        "{%0,%1,%2,%3}, {%4,%5,%6,%7}, {%8,%9}, {%0,%1,%2,%3};"
        : "+f"(c[0]), "+f"(c[1]), "+f"(c[2]), "+f"(c[3])
        : "r"(a[0]), "r"(a[1]), "r"(a[2]), "r"(a[3]), "r"(b[0]), "r"(b[1]));
}

// ---------------------------------------------------------------------------
// 3xBF16 m16n8k16 GEMM:  C[M,N] = A[M,K] @ B[K,N] + bias[N]
// BM=128, BN=128, BK=32. 256 threads = 8 warps (4 m x 2 n), warp tile 32x64.
// A,B split hi/lo bf16; C = Ah*Bh + Ah*Bl + Al*Bh, fp32 accumulate.
// Smem (u32 words, stride 20 = 16 data + 4 pad; r*20 mod 32 all-distinct):
//   A hi/lo: [128 rows][16 k-pairs]    B hi/lo: [128 n][16 k-pairs]
// k16 fragments: a0/a1 @ k-pair (8ks+q), a2/a3 @ +4; b0 @ (8ks+q), b1 @ +4.
// ---------------------------------------------------------------------------
#define SSTR 20
#define U_AHI 0
#define U_ALO (128 * SSTR)
#define U_BHI (2 * 128 * SSTR)
#define U_BLO (3 * 128 * SSTR)
#define SMEM_WORDS (4 * 128 * SSTR)
#define SMEM_BYTES (SMEM_WORDS * 4)

__global__ __launch_bounds__(256, 2) void gemm_mma(
    int M, int N, int K,
    const float* __restrict__ A,
    const float* __restrict__ B,
    const float* __restrict__ bias,
    float* __restrict__ C)
{
    extern __shared__ uint32_t su[];
    uint32_t* sAhi = su + U_AHI;
    uint32_t* sAlo = su + U_ALO;
    uint32_t* sBhi = su + U_BHI;
    uint32_t* sBlo = su + U_BLO;

    const int tid  = threadIdx.x;
    const int lane = tid & 31;
    const int warp = tid >> 5;
    const int wm   = warp & 3;   // m offset wm*32
    const int wn   = warp >> 2;  // n offset wn*64
    const int bm   = blockIdx.x * 128;
    const int bn   = blockIdx.y * 128;

    float acc[2][8][4];
#pragma unroll
    for (int mt = 0; mt < 2; mt++)
#pragma unroll
        for (int nt = 0; nt < 8; nt++)
#pragma unroll
            for (int i = 0; i < 4; i++) acc[mt][nt][i] = 0.f;

    const int r = lane >> 2;   // 0..7
    const int q = lane & 3;    // 0..3

    for (int c = 0; c < K / 32; c++) {
        const int k0 = c * 32;
        // ---- stage A (128 rows x 32 k), split -> bf16 pairs ----
#pragma unroll
        for (int i = 0; i < 4; i++) {
            const int idx = tid + i * 256;          // 0..1023
            const int row = idx >> 3;               // 0..127
            const int qq  = idx & 7;                // float4 index (k = 4qq)
            float4 v = *(const float4*)(A + (size_t)(bm + row) * K + k0 + qq * 4);
            uint32_t h0, l0, h1, l1;
            split_pair(v.x, v.y, h0, l0);
            split_pair(v.z, v.w, h1, l1);
            uint32_t* ph = sAhi + row * SSTR + qq * 2;
            uint32_t* pl = sAlo + row * SSTR + qq * 2;
            *(uint2*)ph = make_uint2(h0, h1);
            *(uint2*)pl = make_uint2(l0, l1);
        }
        // ---- stage B (32 k x 128 n) -> n-major bf16 k-pairs ----
#pragma unroll
        for (int i = 0; i < 2; i++) {
            const int idx2 = tid + i * 256;         // 0..511
            const int kp = idx2 & 15;               // 0..15
            const int ng = idx2 >> 4;               // 0..31
            const float* b0p = B + (size_t)(k0 + 2 * kp) * N + bn + ng * 4;
            float4 r0 = *(const float4*)b0p;
            float4 r1 = *(const float4*)(b0p + N);
#pragma unroll
            for (int j = 0; j < 4; j++) {
                float e = (&r0.x)[j];      // k = 2kp
                float o = (&r1.x)[j];      // k = 2kp+1
                uint32_t hp, lp;
                split_pair(e, o, hp, lp);
                sBhi[(ng * 4 + j) * SSTR + kp] = hp;
                sBlo[(ng * 4 + j) * SSTR + kp] = lp;
            }
        }
        __syncthreads();

        // ---- compute: 2 k16-steps ----
#pragma unroll
        for (int ks = 0; ks < 2; ks++) {
            const int kp0 = ks * 8 + q;
            uint32_t ah[2][4], al[2][4];
            {
                const int arow = wm * 32 + r;
#pragma unroll
                for (int mt = 0; mt < 2; mt++) {
                    const int base = (arow + mt * 16) * SSTR + kp0;
                    ah[mt][0] = sAhi[base];
                    ah[mt][1] = sAhi[base + 8 * SSTR];
                    ah[mt][2] = sAhi[base + 4];
                    ah[mt][3] = sAhi[base + 8 * SSTR + 4];
                    al[mt][0] = sAlo[base];
                    al[mt][1] = sAlo[base + 8 * SSTR];
                    al[mt][2] = sAlo[base + 4];
                    al[mt][3] = sAlo[base + 8 * SSTR + 4];
                }
            }
#pragma unroll
            for (int ng = 0; ng < 2; ng++) {
                uint32_t bh[4][2], bl[4][2];
                {
                    const int nbase = (wn * 64 + ng * 32 + r) * SSTR + kp0;
#pragma unroll
                    for (int nt = 0; nt < 4; nt++) {
                        const int o0 = nbase + nt * 8 * SSTR;
                        bh[nt][0] = sBhi[o0];
                        bh[nt][1] = sBhi[o0 + 4];
                        bl[nt][0] = sBlo[o0];
                        bl[nt][1] = sBlo[o0 + 4];
                    }
                }
#pragma unroll
                for (int mt = 0; mt < 2; mt++)
#pragma unroll
                    for (int nt = 0; nt < 4; nt++) {
                        float* a4 = acc[mt][ng * 4 + nt];
                        mma_bf16_k16(a4, ah[mt], bh[nt]);
                        mma_bf16_k16(a4, ah[mt], bl[nt]);
                        mma_bf16_k16(a4, al[mt], bh[nt]);
                    }
            }
        }
        __syncthreads();
    }

    // ---- epilogue: direct global stores with bias ----
#pragma unroll
    for (int mt = 0; mt < 2; mt++) {
        const int row0 = bm + wm * 32 + mt * 16 + r;
#pragma unroll
        for (int nt = 0; nt < 8; nt++) {
            const int col0 = bn + wn * 64 + nt * 8 + q * 2;
            const float2 bv = *(const float2*)(bias + col0);
            float2 o0, o1;
            o0.x = acc[mt][nt][0] + bv.x; o0.y = acc[mt][nt][1] + bv.y;
            o1.x = acc[mt][nt][2] + bv.x; o1.y = acc[mt][nt][3] + bv.y;
            *(float2*)(C + (size_t)row0 * N + col0) = o0;
            *(float2*)(C + (size_t)(row0 + 8) * N + col0) = o1;
        }
    }
}

// ---------------------------------------------------------------------------
// Windowed attention: one block per (window, head). 64 threads; threads 0..48
// each own one query row.
// ---------------------------------------------------------------------------
__global__ __launch_bounds__(64) void attn_kernel(
    const float* __restrict__ qkv,
    const float* __restrict__ pos,
    float* __restrict__ att)
{
    __shared__ float sq[WT * HD];
    __shared__ float sk[WT * HD];
    __shared__ float sv[WT * HD];
    __shared__ float ss[WT * WT];
    __shared__ float spos[169];

    const int id   = blockIdx.x;
    const int head = id & 7;
    const int j    = (id >> 3) & 7;
    const int i    = (id >> 6) & 7;
    const int b    = id >> 9;
    const int tid  = threadIdx.x;
    const int base = b * 3136 + i * 7 * 56 + j * 7;

    for (int idx = tid; idx < WT * HD; idx += 64) {
        const int t = idx >> 5, d = idx & 31;
        const size_t row = (size_t)(base + (t / 7) * 56 + (t % 7)) * QKVD
                         + head * HD + d;
        sq[idx] = qkv[row];
        sk[idx] = qkv[row + 256];
        sv[idx] = qkv[row + 512];
    }
    for (int idx = tid; idx < 169; idx += 64) spos[idx] = pos[idx];
    __syncthreads();

    if (tid < WT) {
        float qr[HD];
#pragma unroll
        for (int d = 0; d < HD; d++) qr[d] = sq[tid * HD + d];

        const int idxr = tid / 7 + tid % 7;
        const float* prow = spos + idxr * 13;
        const float4* sk4 = (const float4*)sk;
        const float4* sv4 = (const float4*)sv;

        float mx = -1e30f;
#pragma unroll 7
        for (int l = 0; l < WT; l++) {
            float a = 0.f;
#pragma unroll
            for (int d4 = 0; d4 < 8; d4++) {
                float4 kv = sk4[l * 8 + d4];
                a += qr[d4 * 4 + 0] * kv.x + qr[d4 * 4 + 1] * kv.y
                   + qr[d4 * 4 + 2] * kv.z + qr[d4 * 4 + 3] * kv.w;
            }
            a = a * SCALE + prow[l / 7 + l % 7];
            ss[tid * WT + l] = a;
            mx = fmaxf(mx, a);
        }

        float sum = 0.f;
#pragma unroll 7
        for (int l = 0; l < WT; l++) {
            float e = __expf(ss[tid * WT + l] - mx);
            ss[tid * WT + l] = e;
            sum += e;
        }
        const float inv = 1.f / sum;

        float acc[HD];
#pragma unroll
        for (int d = 0; d < HD; d++) acc[d] = 0.f;

#pragma unroll 7
        for (int l = 0; l < WT; l++) {
            const float p = ss[tid * WT + l];
#pragma unroll
            for (int d4 = 0; d4 < 8; d4++) {
                float4 vv = sv4[l * 8 + d4];
                acc[d4 * 4 + 0] += p * vv.x; acc[d4 * 4 + 1] += p * vv.y;
                acc[d4 * 4 + 2] += p * vv.z; acc[d4 * 4 + 3] += p * vv.w;
            }
        }

        const size_t orow = (size_t)(base + (tid / 7) * 56 + (tid % 7)) * CIN
                          + head * HD;
#pragma unroll
        for (int d4 = 0; d4 < 8; d4++) {
            float4 o;
            o.x = acc[d4 * 4 + 0] * inv; o.y = acc[d4 * 4 + 1] * inv;
            o.z = acc[d4 * 4 + 2] * inv; o.w = acc[d4 * 4 + 3] * inv;
            *(float4*)(att + orow + d4 * 4) = o;
        }
    }
}

// ---------------------------------------------------------------------------
extern "C" void kernel_launch(void* const* d_in, const int* in_sizes, int n_in,
                              void* d_out, int out_size)
{
    const float* x      = (const float*)d_in[0];
    const float* pos    = (const float*)d_in[1];
    const float* w_qkv  = (const float*)d_in[2];
    const float* b_qkv  = (const float*)d_in[3];
    const float* w_out  = (const float*)d_in[4];
    const float* b_out  = (const float*)d_in[5];
    float* out = (float*)d_out;

    float *qkvp, *attp;
    cudaGetSymbolAddress((void**)&qkvp, g_qkv);
    cudaGetSymbolAddress((void**)&attp, g_att);

    cudaFuncSetAttribute(gemm_mma, cudaFuncAttributeMaxDynamicSharedMemorySize,
                         SMEM_BYTES);

    // 1) qkv = x @ w_qkv + b_qkv     [200704,256]@[256,768]
    {
        dim3 grid(TOK / 128, QKVD / 128);
        gemm_mma<<<grid, 256, SMEM_BYTES>>>(TOK, QKVD, CIN, x, w_qkv, b_qkv, qkvp);
    }
    // 2) windowed attention
    attn_kernel<<<NWIN * NHEAD, 64>>>(qkvp, pos, attp);
    // 3) out = att @ w_out + b_out   [200704,256]@[256,256]
    {
        dim3 grid(TOK / 128, CIN / 128);
        gemm_mma<<<grid, 256, SMEM_BYTES>>>(TOK, CIN, CIN, attp, w_out, b_out, out);
    }
}

// round 17
// speedup vs baseline: 1.3479x; 1.1209x over previous
#include <cuda_runtime.h>
#include <cstdint>

#define TOK   200704       // 64*56*56 tokens
#define CIN   256
#define QKVD  768
#define KHALF 128          // CIN/2 k-pairs
#define NHEAD 8
#define HD    32
#define WT    49
#define NWIN  4096
#define SCALE 5.656854249f // sqrt(32) -- reference MULTIPLIES by sqrt(hd)

// ---------------- scratch (static device globals; no allocs allowed) -------
__device__ __align__(16) float    g_qkv[(size_t)TOK * QKVD];
__device__ __align__(16) uint32_t g_xhi[(size_t)TOK * KHALF];
__device__ __align__(16) uint32_t g_xlo[(size_t)TOK * KHALF];
__device__ __align__(16) uint32_t g_ahi[(size_t)TOK * KHALF];   // att out hi
__device__ __align__(16) uint32_t g_alo[(size_t)TOK * KHALF];   // att out lo
__device__ __align__(16) uint32_t g_w1h[(size_t)QKVD * KHALF];
__device__ __align__(16) uint32_t g_w1l[(size_t)QKVD * KHALF];
__device__ __align__(16) uint32_t g_w2h[(size_t)CIN * KHALF];
__device__ __align__(16) uint32_t g_w2l[(size_t)CIN * KHALF];

// ---------------- helpers ---------------------------------------------------
__device__ __forceinline__ uint32_t pack_bf16(float lo_elem, float hi_elem) {
    uint32_t d;
    asm("cvt.rn.bf16x2.f32 %0, %1, %2;" : "=r"(d) : "f"(hi_elem), "f"(lo_elem));
    return d;
}
__device__ __forceinline__ void split_pair(float e, float o,
                                           uint32_t& hp, uint32_t& lp) {
    hp = pack_bf16(e, o);
    float ef = __uint_as_float(hp << 16);
    float of = __uint_as_float(hp & 0xFFFF0000u);
    lp = pack_bf16(e - ef, o - of);
}
__device__ __forceinline__ void mma_bf16_k16(float* c, const uint32_t* a,
                                             const uint32_t* b) {
    asm volatile(
        "mma.sync.aligned.m16n8k16.row.col.f32.bf16.bf16.f32 "
        "{%0,%1,%2,%3}, {%4,%5,%6,%7}, {%8,%9}, {%0,%1,%2,%3};"
        : "+f"(c[0]), "+f"(c[1]), "+f"(c[2]), "+f"(c[3])
        : "r"(a[0]), "r"(a[1]), "r"(a[2]), "r"(a[3]), "r"(b[0]), "r"(b[1]));
}
__device__ __forceinline__ uint32_t smem_u32(const void* p) {
    uint32_t a;
    asm("{ .reg .u64 t; cvta.to.shared.u64 t, %1; cvt.u32.u64 %0, t; }"
        : "=r"(a) : "l"(p));
    return a;
}
__device__ __forceinline__ void cp16(uint32_t dst, const void* src) {
    asm volatile("cp.async.cg.shared.global [%0], [%1], 16;"
                 :: "r"(dst), "l"(src));
}

// ---------------------------------------------------------------------------
// Prep: x [TOK,256] fp32 -> hi/lo bf16 k-pair-packed [TOK][128 kp]
// ---------------------------------------------------------------------------
__global__ void prep_x(const float4* __restrict__ x4,
                       uint2* __restrict__ xhi2, uint2* __restrict__ xlo2,
                       size_t n4) {
    size_t idx = (size_t)blockIdx.x * blockDim.x + threadIdx.x;
    if (idx >= n4) return;
    float4 v = x4[idx];
    uint32_t h0, l0, h1, l1;
    split_pair(v.x, v.y, h0, l0);
    split_pair(v.z, v.w, h1, l1);
    xhi2[idx] = make_uint2(h0, h1);
    xlo2[idx] = make_uint2(l0, l1);
}

// Prep: W [K,N] fp32 -> n-major hi/lo [N][K/2 kp]
__global__ void prep_w(const float* __restrict__ W,
                       uint32_t* __restrict__ whi, uint32_t* __restrict__ wlo,
                       int K, int N) {
    int idx = blockIdx.x * blockDim.x + threadIdx.x;
    if (idx >= N * (K / 2)) return;
    int n = idx / (K / 2), kp = idx % (K / 2);
    float e = W[(size_t)(2 * kp) * N + n];
    float o = W[(size_t)(2 * kp + 1) * N + n];
    uint32_t hp, lp;
    split_pair(e, o, hp, lp);
    whi[idx] = hp;
    wlo[idx] = lp;
}

// ---------------------------------------------------------------------------
// 3xBF16 m16n8k16 GEMM from pre-split operands, cp.async double-buffered.
// C[M,N] = A[M,K] @ B[K,N] + bias[N].  BM=BN=128, BK=32 (16 kp per chunk).
// Smem per stage (u32 words, stride 20): A hi/lo [128][16], B hi/lo [128][16].
// ---------------------------------------------------------------------------
#define SSTR 20
#define U_AHI 0
#define U_ALO (128 * SSTR)
#define U_BHI (2 * 128 * SSTR)
#define U_BLO (3 * 128 * SSTR)
#define BUF_WORDS (4 * 128 * SSTR)
#define SMEM_BYTES (2 * BUF_WORDS * 4)

__global__ __launch_bounds__(256, 2) void gemm_mma(
    int M, int N, int K,
    const uint32_t* __restrict__ Ahi, const uint32_t* __restrict__ Alo,
    const uint32_t* __restrict__ Bhi, const uint32_t* __restrict__ Blo,
    const float* __restrict__ bias,
    float* __restrict__ C)
{
    extern __shared__ uint32_t su[];
    const uint32_t sbase = smem_u32(su);
    const int kh = K >> 1;            // k-pairs per row

    const int tid  = threadIdx.x;
    const int lane = tid & 31;
    const int warp = tid >> 5;
    const int wm   = warp & 3;
    const int wn   = warp >> 2;
    const int bm   = blockIdx.x * 128;
    const int bn   = blockIdx.y * 128;

    float acc[2][8][4];
#pragma unroll
    for (int mt = 0; mt < 2; mt++)
#pragma unroll
        for (int nt = 0; nt < 8; nt++)
#pragma unroll
            for (int i = 0; i < 4; i++) acc[mt][nt][i] = 0.f;

    const int r = lane >> 2;
    const int q = lane & 3;

    const int nchunk = K / 32;

    // stage chunk c into buffer buf: 8 x 16B cp.async per thread
    auto stage = [&](int c, int buf) {
        const uint32_t b0 = sbase + buf * (BUF_WORDS * 4);
        const int kbase = c * 16;
#pragma unroll
        for (int i = 0; i < 2; i++) {
            const int idx = tid + i * 256;     // 0..511
            const int row = idx >> 2;          // 0..127
            const int seg = idx & 3;           // 0..3 (4 u32 each)
            const uint32_t soff = (row * SSTR + seg * 4) * 4;
            const size_t goffA = (size_t)(bm + row) * kh + kbase + seg * 4;
            const size_t goffB = (size_t)(bn + row) * kh + kbase + seg * 4;
            cp16(b0 + U_AHI * 4 + soff, Ahi + goffA);
            cp16(b0 + U_ALO * 4 + soff, Alo + goffA);
            cp16(b0 + U_BHI * 4 + soff, Bhi + goffB);
            cp16(b0 + U_BLO * 4 + soff, Blo + goffB);
        }
        asm volatile("cp.async.commit_group;" ::: "memory");
    };

    stage(0, 0);

    for (int c = 0; c < nchunk; c++) {
        const int cur = c & 1;
        if (c + 1 < nchunk) {
            stage(c + 1, cur ^ 1);
            asm volatile("cp.async.wait_group 1;" ::: "memory");
        } else {
            asm volatile("cp.async.wait_group 0;" ::: "memory");
        }
        __syncthreads();

        const uint32_t* sAhi = su + cur * BUF_WORDS + U_AHI;
        const uint32_t* sAlo = su + cur * BUF_WORDS + U_ALO;
        const uint32_t* sBhi = su + cur * BUF_WORDS + U_BHI;
        const uint32_t* sBlo = su + cur * BUF_WORDS + U_BLO;

#pragma unroll
        for (int ks = 0; ks < 2; ks++) {
            const int kp0 = ks * 8 + q;
            uint32_t ah[2][4], al[2][4];
            {
                const int arow = wm * 32 + r;
#pragma unroll
                for (int mt = 0; mt < 2; mt++) {
                    const int base = (arow + mt * 16) * SSTR + kp0;
                    ah[mt][0] = sAhi[base];
                    ah[mt][1] = sAhi[base + 8 * SSTR];
                    ah[mt][2] = sAhi[base + 4];
                    ah[mt][3] = sAhi[base + 8 * SSTR + 4];
                    al[mt][0] = sAlo[base];
                    al[mt][1] = sAlo[base + 8 * SSTR];
                    al[mt][2] = sAlo[base + 4];
                    al[mt][3] = sAlo[base + 8 * SSTR + 4];
                }
            }
#pragma unroll
            for (int ng = 0; ng < 2; ng++) {
                uint32_t bh[4][2], bl[4][2];
                {
                    const int nbase = (wn * 64 + ng * 32 + r) * SSTR + kp0;
#pragma unroll
                    for (int nt = 0; nt < 4; nt++) {
                        const int o0 = nbase + nt * 8 * SSTR;
                        bh[nt][0] = sBhi[o0];
                        bh[nt][1] = sBhi[o0 + 4];
                        bl[nt][0] = sBlo[o0];
                        bl[nt][1] = sBlo[o0 + 4];
                    }
                }
#pragma unroll
                for (int mt = 0; mt < 2; mt++)
#pragma unroll
                    for (int nt = 0; nt < 4; nt++) {
                        float* a4 = acc[mt][ng * 4 + nt];
                        mma_bf16_k16(a4, ah[mt], bh[nt]);
                        mma_bf16_k16(a4, ah[mt], bl[nt]);
                        mma_bf16_k16(a4, al[mt], bh[nt]);
                    }
            }
        }
        __syncthreads();
    }

    // ---- epilogue ----
#pragma unroll
    for (int mt = 0; mt < 2; mt++) {
        const int row0 = bm + wm * 32 + mt * 16 + r;
#pragma unroll
        for (int nt = 0; nt < 8; nt++) {
            const int col0 = bn + wn * 64 + nt * 8 + q * 2;
            const float2 bv = *(const float2*)(bias + col0);
            float2 o0, o1;
            o0.x = acc[mt][nt][0] + bv.x; o0.y = acc[mt][nt][1] + bv.y;
            o1.x = acc[mt][nt][2] + bv.x; o1.y = acc[mt][nt][3] + bv.y;
            *(float2*)(C + (size_t)row0 * N + col0) = o0;
            *(float2*)(C + (size_t)(row0 + 8) * N + col0) = o1;
        }
    }
}

// ---------------------------------------------------------------------------
// Windowed attention; output written pre-split hi/lo (k-pair packed) for gemm3.
// ---------------------------------------------------------------------------
__global__ __launch_bounds__(64) void attn_kernel(
    const float* __restrict__ qkv,
    const float* __restrict__ pos,
    uint32_t* __restrict__ atthi,
    uint32_t* __restrict__ attlo)
{
    __shared__ float sq[WT * HD];
    __shared__ float sk[WT * HD];
    __shared__ float sv[WT * HD];
    __shared__ float ss[WT * WT];
    __shared__ float spos[169];

    const int id   = blockIdx.x;
    const int head = id & 7;
    const int j    = (id >> 3) & 7;
    const int i    = (id >> 6) & 7;
    const int b    = id >> 9;
    const int tid  = threadIdx.x;
    const int base = b * 3136 + i * 7 * 56 + j * 7;

    for (int idx = tid; idx < WT * HD; idx += 64) {
        const int t = idx >> 5, d = idx & 31;
        const size_t row = (size_t)(base + (t / 7) * 56 + (t % 7)) * QKVD
                         + head * HD + d;
        sq[idx] = qkv[row];
        sk[idx] = qkv[row + 256];
        sv[idx] = qkv[row + 512];
    }
    for (int idx = tid; idx < 169; idx += 64) spos[idx] = pos[idx];
    __syncthreads();

    if (tid < WT) {
        float qr[HD];
#pragma unroll
        for (int d = 0; d < HD; d++) qr[d] = sq[tid * HD + d];

        const int idxr = tid / 7 + tid % 7;
        const float* prow = spos + idxr * 13;
        const float4* sk4 = (const float4*)sk;
        const float4* sv4 = (const float4*)sv;

        float mx = -1e30f;
#pragma unroll 7
        for (int l = 0; l < WT; l++) {
            float a = 0.f;
#pragma unroll
            for (int d4 = 0; d4 < 8; d4++) {
                float4 kv = sk4[l * 8 + d4];
                a += qr[d4 * 4 + 0] * kv.x + qr[d4 * 4 + 1] * kv.y
                   + qr[d4 * 4 + 2] * kv.z + qr[d4 * 4 + 3] * kv.w;
            }
            a = a * SCALE + prow[l / 7 + l % 7];
            ss[tid * WT + l] = a;
            mx = fmaxf(mx, a);
        }

        float sum = 0.f;
#pragma unroll 7
        for (int l = 0; l < WT; l++) {
            float e = __expf(ss[tid * WT + l] - mx);
            ss[tid * WT + l] = e;
            sum += e;
        }
        const float inv = 1.f / sum;

        float acc[HD];
#pragma unroll
        for (int d = 0; d < HD; d++) acc[d] = 0.f;

#pragma unroll 7
        for (int l = 0; l < WT; l++) {
            const float p = ss[tid * WT + l];
#pragma unroll
            for (int d4 = 0; d4 < 8; d4++) {
                float4 vv = sv4[l * 8 + d4];
                acc[d4 * 4 + 0] += p * vv.x; acc[d4 * 4 + 1] += p * vv.y;
                acc[d4 * 4 + 2] += p * vv.z; acc[d4 * 4 + 3] += p * vv.w;
            }
        }

        // write pre-split hi/lo, k-pair packed: row = token, kp = head*16 + j
        const size_t orow = (size_t)(base + (tid / 7) * 56 + (tid % 7)) * KHALF
                          + head * 16;
#pragma unroll
        for (int p2 = 0; p2 < 16; p2++) {
            uint32_t hp, lp;
            split_pair(acc[2 * p2] * inv, acc[2 * p2 + 1] * inv, hp, lp);
            atthi[orow + p2] = hp;
            attlo[orow + p2] = lp;
        }
    }
}

// ---------------------------------------------------------------------------
extern "C" void kernel_launch(void* const* d_in, const int* in_sizes, int n_in,
                              void* d_out, int out_size)
{
    const float* x      = (const float*)d_in[0];
    const float* pos    = (const float*)d_in[1];
    const float* w_qkv  = (const float*)d_in[2];
    const float* b_qkv  = (const float*)d_in[3];
    const float* w_out  = (const float*)d_in[4];
    const float* b_out  = (const float*)d_in[5];
    float* out = (float*)d_out;

    float *qkvp;
    uint32_t *xhi, *xlo, *ahi, *alo, *w1h, *w1l, *w2h, *w2l;
    cudaGetSymbolAddress((void**)&qkvp, g_qkv);
    cudaGetSymbolAddress((void**)&xhi, g_xhi);
    cudaGetSymbolAddress((void**)&xlo, g_xlo);
    cudaGetSymbolAddress((void**)&ahi, g_ahi);
    cudaGetSymbolAddress((void**)&alo, g_alo);
    cudaGetSymbolAddress((void**)&w1h, g_w1h);
    cudaGetSymbolAddress((void**)&w1l, g_w1l);
    cudaGetSymbolAddress((void**)&w2h, g_w2h);
    cudaGetSymbolAddress((void**)&w2l, g_w2l);

    cudaFuncSetAttribute(gemm_mma, cudaFuncAttributeMaxDynamicSharedMemorySize,
                         SMEM_BYTES);

    // 0) pre-split operands
    {
        size_t n4 = (size_t)TOK * 64;
        prep_x<<<(unsigned)((n4 + 255) / 256), 256>>>(
            (const float4*)x, (uint2*)xhi, (uint2*)xlo, n4);
        prep_w<<<(QKVD * KHALF + 255) / 256, 256>>>(w_qkv, w1h, w1l, CIN, QKVD);
        prep_w<<<(CIN * KHALF + 255) / 256, 256>>>(w_out, w2h, w2l, CIN, CIN);
    }
    // 1) qkv = x @ w_qkv + b_qkv
    {
        dim3 grid(TOK / 128, QKVD / 128);
        gemm_mma<<<grid, 256, SMEM_BYTES>>>(TOK, QKVD, CIN,
                                            xhi, xlo, w1h, w1l, b_qkv, qkvp);
    }
    // 2) windowed attention (writes pre-split att)
    attn_kernel<<<NWIN * NHEAD, 64>>>(qkvp, pos, ahi, alo);
    // 3) out = att @ w_out + b_out
    {
        dim3 grid(TOK / 128, CIN / 128);
        gemm_mma<<<grid, 256, SMEM_BYTES>>>(TOK, CIN, CIN,
                                            ahi, alo, w2h, w2l, b_out, out);
    }
}